// round 11
// baseline (speedup 1.0000x reference)
#include <cuda_runtime.h>
#include <cuda_fp16.h>
#include <cstdint>

#define TSEQ 2048
#define BATCH 8
#define DM 1024
#define HD 128
#define MTOT (BATCH * TSEQ)

// fp16 pre-converted inputs
__device__ __align__(16) __half g_xh[MTOT * DM];   // x hi
__device__ __align__(16) __half g_xl[MTOT * DM];   // x lo (for q)
__device__ __align__(16) __half g_wh[3 * HD * DM]; // Wq(scaled),Wk,Wv fp16
// fp16 scratch: Q split-2 (hi+lo), K/V single. Q pre-scaled by 1/sqrt(HD).
__device__ __align__(16) __half g_qh[MTOT * HD];
__device__ __align__(16) __half g_ql[MTOT * HD];
__device__ __align__(16) __half g_kh[MTOT * HD];
__device__ __align__(16) __half g_vh[MTOT * HD];

__device__ __forceinline__ uint32_t smem_u32(const void* p) {
  return (uint32_t)__cvta_generic_to_shared(p);
}

__device__ __forceinline__ void mma_fp16(float* d, const uint32_t* a,
                                         const uint32_t* b) {
  asm volatile(
      "mma.sync.aligned.m16n8k16.row.col.f32.f16.f16.f32 "
      "{%0,%1,%2,%3}, {%4,%5,%6,%7}, {%8,%9}, {%0,%1,%2,%3};\n"
      : "+f"(d[0]), "+f"(d[1]), "+f"(d[2]), "+f"(d[3])
      : "r"(a[0]), "r"(a[1]), "r"(a[2]), "r"(a[3]), "r"(b[0]), "r"(b[1]));
}

__device__ __forceinline__ void ldm_x4(uint32_t* r, uint32_t addr) {
  asm volatile(
      "ldmatrix.sync.aligned.m8n8.x4.shared.b16 {%0,%1,%2,%3}, [%4];"
      : "=r"(r[0]), "=r"(r[1]), "=r"(r[2]), "=r"(r[3]) : "r"(addr));
}
__device__ __forceinline__ void ldm_x4_t(uint32_t* r, uint32_t addr) {
  asm volatile(
      "ldmatrix.sync.aligned.m8n8.x4.trans.shared.b16 {%0,%1,%2,%3}, [%4];"
      : "=r"(r[0]), "=r"(r[1]), "=r"(r[2]), "=r"(r[3]) : "r"(addr));
}

#define CP16(dst, src) \
  asm volatile("cp.async.cg.shared.global [%0], [%1], 16;" :: "r"(dst), "l"(src))
#define CP_COMMIT() asm volatile("cp.async.commit_group;" ::: "memory")
#define CP_WAIT0() asm volatile("cp.async.wait_group 0;" ::: "memory")
#define CP_WAIT1() asm volatile("cp.async.wait_group 1;" ::: "memory")

// 8 fp32 -> 8 fp16 hi + 8 fp16 lo
__device__ __forceinline__ void cvt8h(float4 a0, float4 a1, uint4& hi, uint4& lo) {
  __half2 h0 = __floats2half2_rn(a0.x, a0.y);
  __half2 h1 = __floats2half2_rn(a0.z, a0.w);
  __half2 h2 = __floats2half2_rn(a1.x, a1.y);
  __half2 h3 = __floats2half2_rn(a1.z, a1.w);
  __half2 l0 = __floats2half2_rn(a0.x - __low2float(h0), a0.y - __high2float(h0));
  __half2 l1 = __floats2half2_rn(a0.z - __low2float(h1), a0.w - __high2float(h1));
  __half2 l2 = __floats2half2_rn(a1.x - __low2float(h2), a1.y - __high2float(h2));
  __half2 l3 = __floats2half2_rn(a1.z - __low2float(h3), a1.w - __high2float(h3));
  hi = make_uint4(*(uint32_t*)&h0, *(uint32_t*)&h1, *(uint32_t*)&h2, *(uint32_t*)&h3);
  lo = make_uint4(*(uint32_t*)&l0, *(uint32_t*)&l1, *(uint32_t*)&l2, *(uint32_t*)&l3);
}
// 8 fp32 -> 8 fp16 (single)
__device__ __forceinline__ uint4 cvt8s(float4 a0, float4 a1) {
  __half2 h0 = __floats2half2_rn(a0.x, a0.y);
  __half2 h1 = __floats2half2_rn(a0.z, a0.w);
  __half2 h2 = __floats2half2_rn(a1.x, a1.y);
  __half2 h3 = __floats2half2_rn(a1.z, a1.w);
  return make_uint4(*(uint32_t*)&h0, *(uint32_t*)&h1, *(uint32_t*)&h2,
                    *(uint32_t*)&h3);
}

// ---------------------------------------------------------------------------
// Kernel 0: pre-convert x -> (xh, xl) fp16 and W -> fp16 (Wq scaled by
// 1/sqrt(HD)). Pure streaming. Blocks [0,4096): x; [4096,4192): W.
// ---------------------------------------------------------------------------
__global__ __launch_bounds__(512) void cvt_pre(
    const float* __restrict__ x, const float* __restrict__ Wq,
    const float* __restrict__ Wk, const float* __restrict__ Wv) {
  const int bid = blockIdx.x, tid = threadIdx.x;
  if (bid < 4096) {
    size_t i8 = ((size_t)bid * 512 + tid) * 8;  // covers 16M floats exactly
    float4 a0 = *(const float4*)(x + i8);
    float4 a1 = *(const float4*)(x + i8 + 4);
    uint4 hi, lo;
    cvt8h(a0, a1, hi, lo);
    *(uint4*)(g_xh + i8) = hi;
    *(uint4*)(g_xl + i8) = lo;
  } else {
    size_t i8 = ((size_t)(bid - 4096) * 512 + tid) * 8;  // 393216 floats exactly
    int yid = (int)(i8 >> 17);       // / (HD*DM)
    size_t off = i8 & 131071;
    const float* W = (yid == 0) ? Wq : (yid == 1 ? Wk : Wv);
    const float s = (yid == 0) ? 0.08838834764831845f : 1.0f;
    float4 a0 = *(const float4*)(W + off);
    float4 a1 = *(const float4*)(W + off + 4);
    a0.x *= s; a0.y *= s; a0.z *= s; a0.w *= s;
    a1.x *= s; a1.y *= s; a1.z *= s; a1.w *= s;
    *(uint4*)(g_wh + (size_t)yid * 131072 + off) = cvt8s(a0, a1);
  }
}

// ---------------------------------------------------------------------------
// Kernel 1: QKV projection, pure fp16 HMMA, cp.async double-buffered.
//   q (y=0): (xh + xl) * W   (2 MMAs)
//   k,v    : xh * W          (1 MMA)
// Grid (128,3), 512 thr, 2 CTAs/SM. BK=32, 80B row stride.
// Loader: 128 rows x 4 chunks(16B) per tile = 512 chunks = 1/thread/tile.
// ---------------------------------------------------------------------------
#define RSTRIDE 80
#define TILE_B (128 * RSTRIDE)  // 10240
#define NBUF_B (3 * TILE_B)     // Xh, Xl, W slots

__global__ __launch_bounds__(512) void qkv_hmma() {
  extern __shared__ __align__(1024) char smem[];
  const int yid = blockIdx.y;
  const bool useLo = (yid == 0);

  const int tid = threadIdx.x;
  const int lane = tid & 31, wid = tid >> 5;
  const int wm = wid >> 2, wn = wid & 3;
  const int m0 = blockIdx.x * 128;
  const uint32_t sb = smem_u32(smem);

  // cp.async loader role
  const int lrow = tid >> 2, lc = tid & 3;
  const size_t srcX = (size_t)(m0 + lrow) * DM + lc * 8;
  const size_t srcW = (size_t)yid * (HD * DM) + (size_t)lrow * DM + lc * 8;
  const uint32_t stoOff = lrow * RSTRIDE + lc * 16;

  const int lane15 = lane & 15;
  const uint32_t aColOff = (lane >> 4) * 16;
  const uint32_t aRowB = (wm * 32 + lane15) * RSTRIDE;
  const uint32_t bRowB = (wn * 32 + ((lane >> 4) << 3) + (lane & 7)) * RSTRIDE;
  const uint32_t bColOff = ((lane >> 3) & 1) * 16;

  float acc[2][4][4];
#pragma unroll
  for (int i = 0; i < 2; i++)
#pragma unroll
    for (int j = 0; j < 4; j++)
#pragma unroll
      for (int r = 0; r < 4; r++) acc[i][j][r] = 0.f;

  // prologue: tile 0 into buffer 0
  {
    uint32_t d = sb + stoOff;
    CP16(d, g_xh + srcX);
    if (useLo) CP16(d + TILE_B, g_xl + srcX);
    CP16(d + 2 * TILE_B, g_wh + srcW);
    CP_COMMIT();
  }

  for (int kt = 0; kt < 32; kt++) {
    if (kt < 31) {
      uint32_t d = sb + ((kt + 1) & 1) * NBUF_B + stoOff;
      size_t o = (size_t)(kt + 1) * 32;
      CP16(d, g_xh + srcX + o);
      if (useLo) CP16(d + TILE_B, g_xl + srcX + o);
      CP16(d + 2 * TILE_B, g_wh + srcW + o);
      CP_COMMIT();
      CP_WAIT1();
    } else {
      CP_WAIT0();
    }
    __syncthreads();

    const uint32_t bufBase = sb + (kt & 1) * NBUF_B;
#pragma unroll
    for (int s = 0; s < 2; s++) {
      uint32_t ah[2][4], al[2][4], b2[2][4];
#pragma unroll
      for (int i = 0; i < 2; i++) {
        uint32_t aa = bufBase + aRowB + i * (16 * RSTRIDE) + s * 32 + aColOff;
        ldm_x4(ah[i], aa);
        if (useLo) ldm_x4(al[i], aa + TILE_B);
      }
#pragma unroll
      for (int j = 0; j < 2; j++) {
        uint32_t ba =
            bufBase + 2 * TILE_B + bRowB + j * (16 * RSTRIDE) + s * 32 + bColOff;
        ldm_x4(b2[j], ba);
      }
#pragma unroll
      for (int i = 0; i < 2; i++)
#pragma unroll
        for (int jj = 0; jj < 4; jj++) {
          const uint32_t* bp = &b2[jj >> 1][(jj & 1) * 2];
          mma_fp16(acc[i][jj], ah[i], bp);
          if (useLo) mma_fp16(acc[i][jj], al[i], bp);
        }
    }
    __syncthreads();  // all reads of this buffer done before next cp overwrites
  }

  const int g = lane >> 2, tig = lane & 3;
  __half* oh = (yid == 0) ? g_qh : (yid == 1 ? g_kh : g_vh);
#pragma unroll
  for (int i = 0; i < 2; i++) {
    int r0 = m0 + wm * 32 + i * 16 + g;
#pragma unroll
    for (int jj = 0; jj < 4; jj++) {
      int col = wn * 32 + jj * 8 + 2 * tig;
      float v0 = acc[i][jj][0], v1 = acc[i][jj][1];
      float v2 = acc[i][jj][2], v3 = acc[i][jj][3];
      __half2 h01 = __floats2half2_rn(v0, v1);
      __half2 h23 = __floats2half2_rn(v2, v3);
      *(uint32_t*)&oh[(size_t)r0 * HD + col] = *(uint32_t*)&h01;
      *(uint32_t*)&oh[(size_t)(r0 + 8) * HD + col] = *(uint32_t*)&h23;
      if (yid == 0) {
        __half2 l01 =
            __floats2half2_rn(v0 - __low2float(h01), v1 - __high2float(h01));
        __half2 l23 =
            __floats2half2_rn(v2 - __low2float(h23), v3 - __high2float(h23));
        *(uint32_t*)&g_ql[(size_t)r0 * HD + col] = *(uint32_t*)&l01;
        *(uint32_t*)&g_ql[(size_t)(r0 + 8) * HD + col] = *(uint32_t*)&l23;
      }
    }
  }
}

// ---------------------------------------------------------------------------
// Kernel 2: causal flash attention (unchanged, known-good 76.2us).
// fp16 HMMA: S = (Qh+Ql)K (2 MMAs), O += P_fp16 V (1 MMA). 512 thr,
// cp.async double-buffered KV, paired q-tiles: 33 iters/CTA, grid (16,8).
// ---------------------------------------------------------------------------
#define QSTR 272
#define PSTR 144
#define KVB_K 17408
#define KVSTG 34816
#define OFF_KV 34816
#define OFF_P (OFF_KV + 2 * KVSTG)   // 104448
#define OFF_MS (OFF_P + 9216)        // 113664
#define ATT_SMEM (OFF_MS + 1024)     // 114688

__global__ __launch_bounds__(512) void attn_mma(float* __restrict__ out) {
  extern __shared__ __align__(16) char smA[];
  const uint32_t sb = smem_u32(smA);
  float* msm = (float*)(smA + OFF_MS);

  const int tid = threadIdx.x, lane = tid & 31, wid = tid >> 5;
  const int wm = wid & 3, wn = wid >> 2;
  const int g = lane >> 2, tig = lane & 3;
  const int b = blockIdx.y;

  const int aRow = lane & 15;
  const int aCol = (lane >> 4) * 16;
  const int bRow = ((lane >> 4) << 3) + (lane & 7);
  const int bCol = ((lane >> 3) & 1) * 16;
  const int vRow = (lane & 7) + (((lane >> 3) & 1) << 3);
  const int vCol = (lane >> 4) * 8;
  const int rA = 16 * wm + g;

  const int ldRow = tid >> 3, ldC = tid & 7;
  const uint32_t ldDst = ldRow * QSTR + ldC * 16;
  const size_t ldSrc = (size_t)ldRow * HD + ldC * 8;

  for (int phse = 0; phse < 2; phse++) {
    const int qt = phse ? (31 - blockIdx.x) : blockIdx.x;
    const size_t qoff = ((size_t)b * TSEQ + (size_t)qt * 64) * HD;
    __syncthreads();
    {
      const uint4* qhp = (const uint4*)(g_qh + qoff);
      const uint4* qlp = (const uint4*)(g_ql + qoff);
#pragma unroll
      for (int it = 0; it < 2; it++) {
        int idx = tid + it * 512;
        uint32_t d = (idx >> 4) * QSTR + (idx & 15) * 16;
        *(uint4*)(smA + d) = qhp[idx];
        *(uint4*)(smA + KVB_K + d) = qlp[idx];
      }
    }
    {
      const size_t koff = (size_t)b * TSEQ * HD;
      const uint32_t d0 = sb + OFF_KV + ldDst;
      CP16(d0, g_kh + koff + ldSrc);
      CP16(d0 + 128, g_kh + koff + ldSrc + 64);
      CP16(d0 + KVB_K, g_vh + koff + ldSrc);
      CP16(d0 + KVB_K + 128, g_vh + koff + ldSrc + 64);
      CP_COMMIT();
    }

    float O[4][4];
#pragma unroll
    for (int nt = 0; nt < 4; nt++)
#pragma unroll
      for (int r = 0; r < 4; r++) O[nt][r] = 0.f;
    float m_r[2] = {-1e30f, -1e30f}, l_r[2] = {0.f, 0.f};

    for (int kb = 0; kb <= qt; kb++) {
      const uint32_t kvb = sb + OFF_KV + (kb & 1) * KVSTG;
      if (kb < qt) {
        const size_t koff = ((size_t)b * TSEQ + (size_t)(kb + 1) * 64) * HD;
        const uint32_t ob = sb + OFF_KV + ((kb + 1) & 1) * KVSTG + ldDst;
        CP16(ob, g_kh + koff + ldSrc);
        CP16(ob + 128, g_kh + koff + ldSrc + 64);
        CP16(ob + KVB_K, g_vh + koff + ldSrc);
        CP16(ob + KVB_K + 128, g_vh + koff + ldSrc + 64);
        CP_COMMIT();
        CP_WAIT1();
      } else {
        CP_WAIT0();
      }
      __syncthreads();

      float sfr[2][4];
#pragma unroll
      for (int nt = 0; nt < 2; nt++)
#pragma unroll
        for (int r = 0; r < 4; r++) sfr[nt][r] = 0.f;
#pragma unroll
      for (int c = 0; c < 8; c++) {
        uint32_t qh4[4], ql4[4], kh4[4];
        uint32_t qa = sb + (16 * wm + aRow) * QSTR + c * 32 + aCol;
        ldm_x4(qh4, qa);
        ldm_x4(ql4, qa + KVB_K);
        ldm_x4(kh4, kvb + (16 * wn + bRow) * QSTR + c * 32 + bCol);
#pragma unroll
        for (int h = 0; h < 2; h++) {
          mma_fp16(sfr[h], qh4, &kh4[2 * h]);
          mma_fp16(sfr[h], ql4, &kh4[2 * h]);
        }
      }

      if (kb == qt) {
#pragma unroll
        for (int nt = 0; nt < 2; nt++) {
          int colRel = 16 * wn + 8 * nt + 2 * tig;
          if (colRel > rA) sfr[nt][0] = -1e30f;
          if (colRel + 1 > rA) sfr[nt][1] = -1e30f;
          if (colRel > rA + 8) sfr[nt][2] = -1e30f;
          if (colRel + 1 > rA + 8) sfr[nt][3] = -1e30f;
        }
      }

      float mxA = fmaxf(fmaxf(sfr[0][0], sfr[0][1]), fmaxf(sfr[1][0], sfr[1][1]));
      float mxB = fmaxf(fmaxf(sfr[0][2], sfr[0][3]), fmaxf(sfr[1][2], sfr[1][3]));
#pragma unroll
      for (int o = 1; o <= 2; o <<= 1) {
        mxA = fmaxf(mxA, __shfl_xor_sync(0xffffffffu, mxA, o));
        mxB = fmaxf(mxB, __shfl_xor_sync(0xffffffffu, mxB, o));
      }
      if (tig == 0) {
        msm[rA * 4 + wn] = mxA;
        msm[(rA + 8) * 4 + wn] = mxB;
      }
      __syncthreads();
      float nmA = fmaxf(m_r[0],
                        fmaxf(fmaxf(msm[rA * 4 + 0], msm[rA * 4 + 1]),
                              fmaxf(msm[rA * 4 + 2], msm[rA * 4 + 3])));
      float nmB = fmaxf(m_r[1],
                        fmaxf(fmaxf(msm[(rA + 8) * 4 + 0], msm[(rA + 8) * 4 + 1]),
                              fmaxf(msm[(rA + 8) * 4 + 2], msm[(rA + 8) * 4 + 3])));
      float corrA = __expf(m_r[0] - nmA);
      float corrB = __expf(m_r[1] - nmB);
      m_r[0] = nmA;
      m_r[1] = nmB;

      float sumA = 0.f, sumB = 0.f;
#pragma unroll
      for (int nt = 0; nt < 2; nt++) {
        float pa0 = __expf(sfr[nt][0] - nmA), pa1 = __expf(sfr[nt][1] - nmA);
        float pb0 = __expf(sfr[nt][2] - nmB), pb1 = __expf(sfr[nt][3] - nmB);
        sumA += pa0 + pa1;
        sumB += pb0 + pb1;
        int colb = (16 * wn + 8 * nt + 2 * tig) * 2;
        __half2 ha = __floats2half2_rn(pa0, pa1);
        __half2 hb = __floats2half2_rn(pb0, pb1);
        *(uint32_t*)(smA + OFF_P + rA * PSTR + colb) = *(uint32_t*)&ha;
        *(uint32_t*)(smA + OFF_P + (rA + 8) * PSTR + colb) = *(uint32_t*)&hb;
      }
#pragma unroll
      for (int o = 1; o <= 2; o <<= 1) {
        sumA += __shfl_xor_sync(0xffffffffu, sumA, o);
        sumB += __shfl_xor_sync(0xffffffffu, sumB, o);
      }
      l_r[0] = l_r[0] * corrA + sumA;
      l_r[1] = l_r[1] * corrB + sumB;
#pragma unroll
      for (int nt = 0; nt < 4; nt++) {
        O[nt][0] *= corrA;
        O[nt][1] *= corrA;
        O[nt][2] *= corrB;
        O[nt][3] *= corrB;
      }
      __syncthreads();

#pragma unroll
      for (int ck = 0; ck < 4; ck++) {
        uint32_t pfh[4];
        uint32_t ad = sb + OFF_P + (16 * wm + aRow) * PSTR + ck * 32 + aCol;
        ldm_x4(pfh, ad);
#pragma unroll
        for (int pv = 0; pv < 2; pv++) {
          uint32_t vh4[4];
          uint32_t vd = kvb + KVB_K + (16 * ck + vRow) * QSTR +
                        (32 * wn + 16 * pv + vCol) * 2;
          ldm_x4_t(vh4, vd);
#pragma unroll
          for (int h = 0; h < 2; h++) {
            int nt = 2 * pv + h;
            mma_fp16(O[nt], pfh, &vh4[2 * h]);
          }
        }
      }
      __syncthreads();
    }

    if (tig == 0) {
      msm[rA * 4 + wn] = l_r[0];
      msm[(rA + 8) * 4 + wn] = l_r[1];
    }
    __syncthreads();
    float liA = 1.f / (msm[rA * 4 + 0] + msm[rA * 4 + 1] + msm[rA * 4 + 2] +
                       msm[rA * 4 + 3]);
    float liB = 1.f / (msm[(rA + 8) * 4 + 0] + msm[(rA + 8) * 4 + 1] +
                       msm[(rA + 8) * 4 + 2] + msm[(rA + 8) * 4 + 3]);
    const size_t tA = (size_t)b * TSEQ + qt * 64 + rA;
#pragma unroll
    for (int nt = 0; nt < 4; nt++) {
      int col = 32 * wn + 8 * nt + 2 * tig;
      *(float2*)&out[tA * HD + col] = make_float2(O[nt][0] * liA, O[nt][1] * liA);
      *(float2*)&out[(tA + 8) * HD + col] =
          make_float2(O[nt][2] * liB, O[nt][3] * liB);
    }
  }
}

extern "C" void kernel_launch(void* const* d_in, const int* in_sizes, int n_in,
                              void* d_out, int out_size) {
  (void)in_sizes; (void)n_in; (void)out_size;
  const float* x  = (const float*)d_in[0];
  const float* Wq = (const float*)d_in[1];
  const float* Wk = (const float*)d_in[2];
  const float* Wv = (const float*)d_in[3];
  float* out = (float*)d_out;

  cvt_pre<<<4192, 512>>>(x, Wq, Wk, Wv);

  const int SMEMQ = 2 * NBUF_B;  // 61440 B
  cudaFuncSetAttribute(qkv_hmma, cudaFuncAttributeMaxDynamicSharedMemorySize,
                       SMEMQ);
  dim3 g1(128, 3);
  qkv_hmma<<<g1, 512, SMEMQ>>>();

  cudaFuncSetAttribute(attn_mma, cudaFuncAttributeMaxDynamicSharedMemorySize,
                       ATT_SMEM);
  dim3 g2(16, 8);
  attn_mma<<<g2, 512, ATT_SMEM>>>(out);
}

// round 12
// speedup vs baseline: 1.0451x; 1.0451x over previous
#include <cuda_runtime.h>
#include <cuda_fp16.h>
#include <cstdint>

#define TSEQ 2048
#define BATCH 8
#define DM 1024
#define HD 128
#define MTOT (BATCH * TSEQ)

// fp16 scratch: Q split-2 (hi+lo), K/V single. Q pre-scaled by 1/sqrt(HD).
__device__ __align__(16) __half g_qh[MTOT * HD];
__device__ __align__(16) __half g_ql[MTOT * HD];
__device__ __align__(16) __half g_kh[MTOT * HD];
__device__ __align__(16) __half g_vh[MTOT * HD];
// split-KV partials: raw O, row max m, row sum l, for halves 0/1
__device__ __align__(16) float g_po[2][MTOT * HD];
__device__ float g_pm[2][MTOT];
__device__ float g_pl[2][MTOT];

__device__ __forceinline__ uint32_t smem_u32(const void* p) {
  return (uint32_t)__cvta_generic_to_shared(p);
}

__device__ __forceinline__ void mma_fp16(float* d, const uint32_t* a,
                                         const uint32_t* b) {
  asm volatile(
      "mma.sync.aligned.m16n8k16.row.col.f32.f16.f16.f32 "
      "{%0,%1,%2,%3}, {%4,%5,%6,%7}, {%8,%9}, {%0,%1,%2,%3};\n"
      : "+f"(d[0]), "+f"(d[1]), "+f"(d[2]), "+f"(d[3])
      : "r"(a[0]), "r"(a[1]), "r"(a[2]), "r"(a[3]), "r"(b[0]), "r"(b[1]));
}

__device__ __forceinline__ void ldm_x4(uint32_t* r, uint32_t addr) {
  asm volatile(
      "ldmatrix.sync.aligned.m8n8.x4.shared.b16 {%0,%1,%2,%3}, [%4];"
      : "=r"(r[0]), "=r"(r[1]), "=r"(r[2]), "=r"(r[3]) : "r"(addr));
}
__device__ __forceinline__ void ldm_x4_t(uint32_t* r, uint32_t addr) {
  asm volatile(
      "ldmatrix.sync.aligned.m8n8.x4.trans.shared.b16 {%0,%1,%2,%3}, [%4];"
      : "=r"(r[0]), "=r"(r[1]), "=r"(r[2]), "=r"(r[3]) : "r"(addr));
}

#define CP16(dst, src) \
  asm volatile("cp.async.cg.shared.global [%0], [%1], 16;" :: "r"(dst), "l"(src))
#define CP_COMMIT() asm volatile("cp.async.commit_group;" ::: "memory")
#define CP_WAIT0() asm volatile("cp.async.wait_group 0;" ::: "memory")

// 8 fp32 -> 8 fp16 hi + 8 fp16 lo
__device__ __forceinline__ void cvt8h(float4 a0, float4 a1, uint4& hi, uint4& lo) {
  __half2 h0 = __floats2half2_rn(a0.x, a0.y);
  __half2 h1 = __floats2half2_rn(a0.z, a0.w);
  __half2 h2 = __floats2half2_rn(a1.x, a1.y);
  __half2 h3 = __floats2half2_rn(a1.z, a1.w);
  __half2 l0 = __floats2half2_rn(a0.x - __low2float(h0), a0.y - __high2float(h0));
  __half2 l1 = __floats2half2_rn(a0.z - __low2float(h1), a0.w - __high2float(h1));
  __half2 l2 = __floats2half2_rn(a1.x - __low2float(h2), a1.y - __high2float(h2));
  __half2 l3 = __floats2half2_rn(a1.z - __low2float(h3), a1.w - __high2float(h3));
  hi = make_uint4(*(uint32_t*)&h0, *(uint32_t*)&h1, *(uint32_t*)&h2, *(uint32_t*)&h3);
  lo = make_uint4(*(uint32_t*)&l0, *(uint32_t*)&l1, *(uint32_t*)&l2, *(uint32_t*)&l3);
}
// 8 fp32 -> 8 fp16 (single)
__device__ __forceinline__ uint4 cvt8s(float4 a0, float4 a1) {
  __half2 h0 = __floats2half2_rn(a0.x, a0.y);
  __half2 h1 = __floats2half2_rn(a0.z, a0.w);
  __half2 h2 = __floats2half2_rn(a1.x, a1.y);
  __half2 h3 = __floats2half2_rn(a1.z, a1.w);
  return make_uint4(*(uint32_t*)&h0, *(uint32_t*)&h1, *(uint32_t*)&h2,
                    *(uint32_t*)&h3);
}

// ---------------------------------------------------------------------------
// Kernel 1: QKV projection (R10 known-good, ~94us). fp16 HMMA, grid (128,3).
//   q: (xh+xl)*W (2 MMAs);  k,v: xh*W (1 MMA). BK=32, double-buffered smem.
// ---------------------------------------------------------------------------
#define RSTRIDE 80
#define TILE_B (128 * RSTRIDE)  // 10240
#define NBUF_B (3 * TILE_B)

__global__ __launch_bounds__(512) void qkv_hmma(
    const float* __restrict__ x, const float* __restrict__ Wq,
    const float* __restrict__ Wk, const float* __restrict__ Wv) {
  extern __shared__ __align__(1024) char smem[];
  const int yid = blockIdx.y;
  const float* W = (yid == 0) ? Wq : (yid == 1 ? Wk : Wv);
  const bool useLo = (yid == 0);

  const int tid = threadIdx.x;
  const int lane = tid & 31, wid = tid >> 5;
  const int wm = wid >> 2, wn = wid & 3;
  const int m0 = blockIdx.x * 128;
  const uint32_t sb = smem_u32(smem);

  const int lrow = tid >> 2, lc = tid & 3;
  const float* aSrc = x + (size_t)(m0 + lrow) * DM + lc * 8;
  const float* bSrc = W + (size_t)lrow * DM + lc * 8;
  const uint32_t stoOff = lrow * RSTRIDE + lc * 16;

  const int lane15 = lane & 15;
  const uint32_t aColOff = (lane >> 4) * 16;
  const uint32_t aRowB = (wm * 32 + lane15) * RSTRIDE;
  const uint32_t bRowB = (wn * 32 + ((lane >> 4) << 3) + (lane & 7)) * RSTRIDE;
  const uint32_t bColOff = ((lane >> 3) & 1) * 16;

  float acc[2][4][4];
#pragma unroll
  for (int i = 0; i < 2; i++)
#pragma unroll
    for (int j = 0; j < 4; j++)
#pragma unroll
      for (int r = 0; r < 4; r++) acc[i][j][r] = 0.f;

  float4 pA0, pA1, pB0, pB1;
  pA0 = *(const float4*)(aSrc);
  pA1 = *(const float4*)(aSrc + 4);
  pB0 = *(const float4*)(bSrc);
  pB1 = *(const float4*)(bSrc + 4);
  {
    char* p = smem + stoOff;
    if (useLo) {
      uint4 hi, lo;
      cvt8h(pA0, pA1, hi, lo);
      *(uint4*)(p) = hi;
      *(uint4*)(p + TILE_B) = lo;
    } else {
      *(uint4*)(p) = cvt8s(pA0, pA1);
    }
    *(uint4*)(p + 2 * TILE_B) = cvt8s(pB0, pB1);
  }
  __syncthreads();

  for (int kt = 0; kt < 32; kt++) {
    if (kt < 31) {
      const float* a = aSrc + (kt + 1) * 32;
      const float* b = bSrc + (kt + 1) * 32;
      pA0 = *(const float4*)(a);
      pA1 = *(const float4*)(a + 4);
      pB0 = *(const float4*)(b);
      pB1 = *(const float4*)(b + 4);
    }
    const uint32_t bufBase = sb + (kt & 1) * NBUF_B;
#pragma unroll
    for (int s = 0; s < 2; s++) {
      uint32_t ah[2][4], al[2][4], b2[2][4];
#pragma unroll
      for (int i = 0; i < 2; i++) {
        uint32_t aa = bufBase + aRowB + i * (16 * RSTRIDE) + s * 32 + aColOff;
        ldm_x4(ah[i], aa);
        if (useLo) ldm_x4(al[i], aa + TILE_B);
      }
#pragma unroll
      for (int j = 0; j < 2; j++) {
        uint32_t ba =
            bufBase + 2 * TILE_B + bRowB + j * (16 * RSTRIDE) + s * 32 + bColOff;
        ldm_x4(b2[j], ba);
      }
#pragma unroll
      for (int i = 0; i < 2; i++)
#pragma unroll
        for (int jj = 0; jj < 4; jj++) {
          const uint32_t* bp = &b2[jj >> 1][(jj & 1) * 2];
          mma_fp16(acc[i][jj], ah[i], bp);
          if (useLo) mma_fp16(acc[i][jj], al[i], bp);
        }
    }
    if (kt < 31) {
      char* p = smem + ((kt + 1) & 1) * NBUF_B + stoOff;
      if (useLo) {
        uint4 hi, lo;
        cvt8h(pA0, pA1, hi, lo);
        *(uint4*)(p) = hi;
        *(uint4*)(p + TILE_B) = lo;
      } else {
        *(uint4*)(p) = cvt8s(pA0, pA1);
      }
      *(uint4*)(p + 2 * TILE_B) = cvt8s(pB0, pB1);
    }
    __syncthreads();
  }

  const int g = lane >> 2, tig = lane & 3;
  const float qs = (yid == 0) ? 0.08838834764831845f : 1.0f;
  __half* oh = (yid == 0) ? g_qh : (yid == 1 ? g_kh : g_vh);
#pragma unroll
  for (int i = 0; i < 2; i++) {
    int r0 = m0 + wm * 32 + i * 16 + g;
#pragma unroll
    for (int jj = 0; jj < 4; jj++) {
      int col = wn * 32 + jj * 8 + 2 * tig;
      float v0 = acc[i][jj][0] * qs, v1 = acc[i][jj][1] * qs;
      float v2 = acc[i][jj][2] * qs, v3 = acc[i][jj][3] * qs;
      __half2 h01 = __floats2half2_rn(v0, v1);
      __half2 h23 = __floats2half2_rn(v2, v3);
      *(uint32_t*)&oh[(size_t)r0 * HD + col] = *(uint32_t*)&h01;
      *(uint32_t*)&oh[(size_t)(r0 + 8) * HD + col] = *(uint32_t*)&h23;
      if (yid == 0) {
        __half2 l01 =
            __floats2half2_rn(v0 - __low2float(h01), v1 - __high2float(h01));
        __half2 l23 =
            __floats2half2_rn(v2 - __low2float(h23), v3 - __high2float(h23));
        *(uint32_t*)&g_ql[(size_t)r0 * HD + col] = *(uint32_t*)&l01;
        *(uint32_t*)&g_ql[(size_t)(r0 + 8) * HD + col] = *(uint32_t*)&l23;
      }
    }
  }
}

// ---------------------------------------------------------------------------
// Kernel 2: causal flash attention, SPLIT-KV x2. Each CTA = (qt, half, b):
// half0: kb in [0, h), half1: kb in [h, qt+1), h = (qt+2)/2. Partials
// (raw O, m, l) to scratch; merge kernel combines. fp16 HMMA as before.
// Single KV buffer -> smem 79872 -> 2 CTAs/SM. Grid (64, 8) = 512 CTAs,
// heavy-first (qt = 31 - bx/2) for work-steal balance.
// ---------------------------------------------------------------------------
#define QSTR 272
#define PSTR 144
#define KVB_K 17408
#define OFF_KV 34816                 // K at OFF_KV, V at OFF_KV+17408
#define OFF_P (OFF_KV + 2 * KVB_K)   // 69632
#define OFF_MS (OFF_P + 9216)        // 78848
#define ATT_SMEM (OFF_MS + 1024)     // 79872

__global__ __launch_bounds__(512, 2) void attn_mma() {
  extern __shared__ __align__(16) char smA[];
  const uint32_t sb = smem_u32(smA);
  float* msm = (float*)(smA + OFF_MS);

  const int tid = threadIdx.x, lane = tid & 31, wid = tid >> 5;
  const int wm = wid & 3, wn = wid >> 2;
  const int g = lane >> 2, tig = lane & 3;
  const int b = blockIdx.y;
  const int qt = 31 - (blockIdx.x >> 1);
  const int half = blockIdx.x & 1;
  const int hsp = (qt + 2) >> 1;
  const int kb_beg = half ? hsp : 0;
  const int kb_end = half ? (qt + 1) : hsp;

  const int aRow = lane & 15;
  const int aCol = (lane >> 4) * 16;
  const int bRow = ((lane >> 4) << 3) + (lane & 7);
  const int bCol = ((lane >> 3) & 1) * 16;
  const int vRow = (lane & 7) + (((lane >> 3) & 1) << 3);
  const int vCol = (lane >> 4) * 8;
  const int rA = 16 * wm + g;

  const int ldRow = tid >> 3, ldC = tid & 7;
  const uint32_t ldDst = ldRow * QSTR + ldC * 16;
  const size_t ldSrc = (size_t)ldRow * HD + ldC * 8;

  // stage Q hi/lo
  {
    const size_t qoff = ((size_t)b * TSEQ + (size_t)qt * 64) * HD;
    const uint4* qhp = (const uint4*)(g_qh + qoff);
    const uint4* qlp = (const uint4*)(g_ql + qoff);
#pragma unroll
    for (int it = 0; it < 2; it++) {
      int idx = tid + it * 512;
      uint32_t d = (idx >> 4) * QSTR + (idx & 15) * 16;
      *(uint4*)(smA + d) = qhp[idx];
      *(uint4*)(smA + KVB_K + d) = qlp[idx];
    }
  }
  // first KV tile
  if (kb_beg < kb_end) {
    const size_t koff = ((size_t)b * TSEQ + (size_t)kb_beg * 64) * HD;
    const uint32_t d0 = sb + OFF_KV + ldDst;
    CP16(d0, g_kh + koff + ldSrc);
    CP16(d0 + 128, g_kh + koff + ldSrc + 64);
    CP16(d0 + KVB_K, g_vh + koff + ldSrc);
    CP16(d0 + KVB_K + 128, g_vh + koff + ldSrc + 64);
    CP_COMMIT();
  }

  float O[4][4];
#pragma unroll
  for (int nt = 0; nt < 4; nt++)
#pragma unroll
    for (int r = 0; r < 4; r++) O[nt][r] = 0.f;
  float m_r[2] = {-1e30f, -1e30f}, l_r[2] = {0.f, 0.f};

  for (int kb = kb_beg; kb < kb_end; kb++) {
    CP_WAIT0();
    __syncthreads();  // KV (+Q on first iter) visible

    float sfr[2][4];
#pragma unroll
    for (int nt = 0; nt < 2; nt++)
#pragma unroll
      for (int r = 0; r < 4; r++) sfr[nt][r] = 0.f;
#pragma unroll
    for (int c = 0; c < 8; c++) {
      uint32_t qh4[4], ql4[4], kh4[4];
      uint32_t qa = sb + (16 * wm + aRow) * QSTR + c * 32 + aCol;
      ldm_x4(qh4, qa);
      ldm_x4(ql4, qa + KVB_K);
      ldm_x4(kh4, sb + OFF_KV + (16 * wn + bRow) * QSTR + c * 32 + bCol);
#pragma unroll
      for (int h = 0; h < 2; h++) {
        mma_fp16(sfr[h], qh4, &kh4[2 * h]);
        mma_fp16(sfr[h], ql4, &kh4[2 * h]);
      }
    }

    if (kb == qt) {
#pragma unroll
      for (int nt = 0; nt < 2; nt++) {
        int colRel = 16 * wn + 8 * nt + 2 * tig;
        if (colRel > rA) sfr[nt][0] = -1e30f;
        if (colRel + 1 > rA) sfr[nt][1] = -1e30f;
        if (colRel > rA + 8) sfr[nt][2] = -1e30f;
        if (colRel + 1 > rA + 8) sfr[nt][3] = -1e30f;
      }
    }

    float mxA = fmaxf(fmaxf(sfr[0][0], sfr[0][1]), fmaxf(sfr[1][0], sfr[1][1]));
    float mxB = fmaxf(fmaxf(sfr[0][2], sfr[0][3]), fmaxf(sfr[1][2], sfr[1][3]));
#pragma unroll
    for (int o = 1; o <= 2; o <<= 1) {
      mxA = fmaxf(mxA, __shfl_xor_sync(0xffffffffu, mxA, o));
      mxB = fmaxf(mxB, __shfl_xor_sync(0xffffffffu, mxB, o));
    }
    if (tig == 0) {
      msm[rA * 4 + wn] = mxA;
      msm[(rA + 8) * 4 + wn] = mxB;
    }
    __syncthreads();
    float nmA = fmaxf(m_r[0],
                      fmaxf(fmaxf(msm[rA * 4 + 0], msm[rA * 4 + 1]),
                            fmaxf(msm[rA * 4 + 2], msm[rA * 4 + 3])));
    float nmB = fmaxf(m_r[1],
                      fmaxf(fmaxf(msm[(rA + 8) * 4 + 0], msm[(rA + 8) * 4 + 1]),
                            fmaxf(msm[(rA + 8) * 4 + 2], msm[(rA + 8) * 4 + 3])));
    float corrA = __expf(m_r[0] - nmA);
    float corrB = __expf(m_r[1] - nmB);
    m_r[0] = nmA;
    m_r[1] = nmB;

    float sumA = 0.f, sumB = 0.f;
#pragma unroll
    for (int nt = 0; nt < 2; nt++) {
      float pa0 = __expf(sfr[nt][0] - nmA), pa1 = __expf(sfr[nt][1] - nmA);
      float pb0 = __expf(sfr[nt][2] - nmB), pb1 = __expf(sfr[nt][3] - nmB);
      sumA += pa0 + pa1;
      sumB += pb0 + pb1;
      int colb = (16 * wn + 8 * nt + 2 * tig) * 2;
      __half2 ha = __floats2half2_rn(pa0, pa1);
      __half2 hb = __floats2half2_rn(pb0, pb1);
      *(uint32_t*)(smA + OFF_P + rA * PSTR + colb) = *(uint32_t*)&ha;
      *(uint32_t*)(smA + OFF_P + (rA + 8) * PSTR + colb) = *(uint32_t*)&hb;
    }
#pragma unroll
    for (int o = 1; o <= 2; o <<= 1) {
      sumA += __shfl_xor_sync(0xffffffffu, sumA, o);
      sumB += __shfl_xor_sync(0xffffffffu, sumB, o);
    }
    l_r[0] = l_r[0] * corrA + sumA;
    l_r[1] = l_r[1] * corrB + sumB;
#pragma unroll
    for (int nt = 0; nt < 4; nt++) {
      O[nt][0] *= corrA;
      O[nt][1] *= corrA;
      O[nt][2] *= corrB;
      O[nt][3] *= corrB;
    }
    __syncthreads();  // P visible

#pragma unroll
    for (int ck = 0; ck < 4; ck++) {
      uint32_t pfh[4];
      uint32_t ad = sb + OFF_P + (16 * wm + aRow) * PSTR + ck * 32 + aCol;
      ldm_x4(pfh, ad);
#pragma unroll
      for (int pv = 0; pv < 2; pv++) {
        uint32_t vh4[4];
        uint32_t vd = sb + OFF_KV + KVB_K + (16 * ck + vRow) * QSTR +
                      (32 * wn + 16 * pv + vCol) * 2;
        ldm_x4_t(vh4, vd);
#pragma unroll
        for (int h = 0; h < 2; h++) {
          int nt = 2 * pv + h;
          mma_fp16(O[nt], pfh, &vh4[2 * h]);
        }
      }
    }
    __syncthreads();  // all KV/P reads done; buffer free

    if (kb + 1 < kb_end) {
      const size_t koff = ((size_t)b * TSEQ + (size_t)(kb + 1) * 64) * HD;
      const uint32_t d0 = sb + OFF_KV + ldDst;
      CP16(d0, g_kh + koff + ldSrc);
      CP16(d0 + 128, g_kh + koff + ldSrc + 64);
      CP16(d0 + KVB_K, g_vh + koff + ldSrc);
      CP16(d0 + KVB_K + 128, g_vh + koff + ldSrc + 64);
      CP_COMMIT();
    }
  }

  // epilogue: combine per-warp l partials, write raw partials
  if (tig == 0) {
    msm[rA * 4 + wn] = l_r[0];
    msm[(rA + 8) * 4 + wn] = l_r[1];
  }
  __syncthreads();
  float lA = msm[rA * 4 + 0] + msm[rA * 4 + 1] + msm[rA * 4 + 2] + msm[rA * 4 + 3];
  float lB = msm[(rA + 8) * 4 + 0] + msm[(rA + 8) * 4 + 1] +
             msm[(rA + 8) * 4 + 2] + msm[(rA + 8) * 4 + 3];
  const size_t base = (size_t)b * TSEQ + (size_t)qt * 64;
  float* po = g_po[half];
#pragma unroll
  for (int nt = 0; nt < 4; nt++) {
    int col = 32 * wn + 8 * nt + 2 * tig;
    *(float2*)&po[(base + rA) * HD + col] = make_float2(O[nt][0], O[nt][1]);
    *(float2*)&po[(base + rA + 8) * HD + col] = make_float2(O[nt][2], O[nt][3]);
  }
  if (wn == 0 && tig == 0) {
    g_pm[half][base + rA] = m_r[0];
    g_pl[half][base + rA] = lA;
    g_pm[half][base + rA + 8] = m_r[1];
    g_pl[half][base + rA + 8] = lB;
  }
}

// ---------------------------------------------------------------------------
// Kernel 3: merge split-KV partials. out = (a1*O1 + a2*O2)/(a1*l1 + a2*l2).
// ---------------------------------------------------------------------------
__global__ __launch_bounds__(512) void merge_k(float* __restrict__ out) {
  int idx = blockIdx.x * 512 + threadIdx.x;  // 16384 rows x 32 col-groups
  int row = idx >> 5, cg = idx & 31;
  float m1 = g_pm[0][row], m2 = g_pm[1][row];
  float l1 = g_pl[0][row], l2 = g_pl[1][row];
  float ms = fmaxf(m1, m2);
  float a1 = __expf(m1 - ms), a2 = __expf(m2 - ms);
  float li = 1.f / (l1 * a1 + l2 * a2);
  float4 o1 = *(const float4*)&g_po[0][(size_t)row * HD + cg * 4];
  float4 o2 = *(const float4*)&g_po[1][(size_t)row * HD + cg * 4];
  float4 r;
  r.x = (o1.x * a1 + o2.x * a2) * li;
  r.y = (o1.y * a1 + o2.y * a2) * li;
  r.z = (o1.z * a1 + o2.z * a2) * li;
  r.w = (o1.w * a1 + o2.w * a2) * li;
  *(float4*)&out[(size_t)row * HD + cg * 4] = r;
}

extern "C" void kernel_launch(void* const* d_in, const int* in_sizes, int n_in,
                              void* d_out, int out_size) {
  (void)in_sizes; (void)n_in; (void)out_size;
  const float* x  = (const float*)d_in[0];
  const float* Wq = (const float*)d_in[1];
  const float* Wk = (const float*)d_in[2];
  const float* Wv = (const float*)d_in[3];
  float* out = (float*)d_out;

  const int SMEMQ = 2 * NBUF_B;  // 61440 B
  cudaFuncSetAttribute(qkv_hmma, cudaFuncAttributeMaxDynamicSharedMemorySize,
                       SMEMQ);
  dim3 g1(128, 3);
  qkv_hmma<<<g1, 512, SMEMQ>>>(x, Wq, Wk, Wv);

  cudaFuncSetAttribute(attn_mma, cudaFuncAttributeMaxDynamicSharedMemorySize,
                       ATT_SMEM);
  dim3 g2(64, 8);
  attn_mma<<<g2, 512, ATT_SMEM>>>();

  merge_k<<<1024, 512>>>(out);
}